// round 4
// baseline (speedup 1.0000x reference)
#include <cuda_runtime.h>
#include <cstdint>

#define WIDTH  1024
#define HALF   512
#define DEPTH  8
#define BDEPTH 10
#define BATCH  65536

typedef unsigned long long ull;

// Butterfly coefficient table: (c, s) float2 per (step, entry).
//   reg-bit steps:  entry = pairidx*32 + lane        (512 entries/step)
//   lane-bit steps: entry = slot*16 + lanepair       (512 entries/step)
// Packed duplicates are rebuilt in-kernel with MOVs (trades alu for L1 bytes —
// L1 crossbar is the measured bottleneck at 74%).
__device__ float2 g_ctab[DEPTH * BDEPTH * 512];
// quintic params per (act_layer, slot*32+lane): (m,m,nb,nb) with m=slope/scale, nb=-bias/scale
__device__ float4 g_qa[(DEPTH - 1) * 1024];
// (scale, scale)
__device__ float2 g_qs[(DEPTH - 1) * 1024];

// ---------- f32x2 helpers ----------
__device__ __forceinline__ ull pk(float lo, float hi) {
    ull r;
    asm("mov.b64 %0, {%1, %2};" : "=l"(r) : "r"(__float_as_uint(lo)), "r"(__float_as_uint(hi)));
    return r;
}
__device__ __forceinline__ void unpk(ull v, float& lo, float& hi) {
    unsigned a, b;
    asm("mov.b64 {%0, %1}, %2;" : "=r"(a), "=r"(b) : "l"(v));
    lo = __uint_as_float(a);
    hi = __uint_as_float(b);
}
__device__ __forceinline__ ull f2mul(ull a, ull b) {
    ull r;
    asm("mul.rn.f32x2 %0, %1, %2;" : "=l"(r) : "l"(a), "l"(b));
    return r;
}
__device__ __forceinline__ ull f2fma(ull a, ull b, ull c) {
    ull r;
    asm("fma.rn.f32x2 %0, %1, %2, %3;" : "=l"(r) : "l"(a), "l"(b), "l"(c));
    return r;
}
// Compiler fence: bounds load hoisting / in-flight register pressure.
__device__ __forceinline__ void cfence() { asm volatile("" ::: "memory"); }

// ---------- prep: all coefficient tables in ONE launch ----------
// Element index p0 (10 bits) maps to (slot v in [0,32), lane l in [0,32)):
//   p0 = (v_hi << 7) | (l << 2) | v_lo   where v = (v_hi<<2)|v_lo
// Step t (in layer) pairs original bit b = 9 - t.
// theta index: j bit k = p0 bit ((k - t) mod 10), k=0..8; theta = bparams[layer][j][t].
#define CT_ELEMS (DEPTH * BDEPTH * 512)
#define Q_ELEMS  ((DEPTH - 1) * 1024)

__global__ void prep_all(const float* __restrict__ bp,
                         const float* __restrict__ bias,
                         const float* __restrict__ slope,
                         const float* __restrict__ scale) {
    int e = blockIdx.x * blockDim.x + threadIdx.x;
    if (e < CT_ELEMS) {
        int T = e >> 9;
        int idx = e & 511;
        int layer = T / BDEPTH;
        int t = T % BDEPTH;
        int b = 9 - t;

        int v0, l0;
        if (b >= 7 || b <= 1) {
            int sbit = (b >= 7) ? (b - 5) : b;
            int m = 1 << sbit;
            int pi = idx >> 5;
            l0 = idx & 31;
            v0 = (pi & (m - 1)) | ((pi & ~(m - 1)) << 1);
        } else {
            int lm = 1 << (b - 2);
            int v = idx >> 4;
            int lp = idx & 15;
            l0 = (lp & (lm - 1)) | ((lp & ~(lm - 1)) << 1);
            v0 = v;
        }
        int p0 = ((v0 >> 2) << 7) | (l0 << 2) | (v0 & 3);

        int j = 0;
#pragma unroll
        for (int k = 0; k < 9; k++) {
            int src = ((k - t) % 10 + 10) % 10;
            j |= ((p0 >> src) & 1) << k;
        }
        float theta = bp[layer * (HALF * BDEPTH) + j * BDEPTH + t];
        float s, c;
        sincosf(theta, &s, &c);
        g_ctab[e] = make_float2(c, s);
    } else if (e < CT_ELEMS + Q_ELEMS) {
        int q = e - CT_ELEMS;
        int act = q >> 10;
        int idx = q & 1023;
        int v = idx >> 5;
        int l = idx & 31;
        int p0 = ((v >> 2) << 7) | (l << 2) | (v & 3);
        float bi = bias[act * WIDTH + p0];
        float sl = slope[act * WIDTH + p0];
        float sc = scale[act * WIDTH + p0];
        g_qa[q] = make_float4(sl / sc, sl / sc, -bi / sc, -bi / sc);
        g_qs[q] = make_float2(sc, sc);
    }
}

// ---------- main kernel ----------
// Each warp processes 4 rows. Thread holds 32 slots x 2 f32x2 values (rows 0,1 | rows 2,3).
// val[v*2 + h].

template <int M>
__device__ __forceinline__ void reg_step(ull (&val)[64], int lane, const float2* __restrict__ ct) {
#pragma unroll
    for (int pi = 0; pi < 16; pi++) {
        const int v0 = (pi & (M - 1)) | ((pi & ~(M - 1)) << 1);
        const int v1 = v0 | M;
        float2 cs = __ldg(ct + pi * 32 + lane);
        ull c2 = pk(cs.x, cs.x);
        ull s2 = pk(cs.y, cs.y);
        ull ns2 = s2 ^ 0x8000000080000000ULL;
#pragma unroll
        for (int h = 0; h < 2; h++) {
            ull x0 = val[v0 * 2 + h];
            ull x1 = val[v1 * 2 + h];
            val[v0 * 2 + h] = f2fma(c2, x0, f2mul(s2, x1));   // n0 =  c*x0 + s*x1
            val[v1 * 2 + h] = f2fma(c2, x1, f2mul(ns2, x0));  // n1 =  c*x1 - s*x0
        }
        if ((pi & 3) == 3) cfence();
    }
}

template <int LM>
__device__ __forceinline__ void lane_step(ull (&val)[64], int lane, const float2* __restrict__ ct) {
    const ull smask = (lane & LM) ? 0x8000000080000000ULL : 0ULL;
    const int lp = (lane & (LM - 1)) | ((lane >> 1) & ~(LM - 1));
#pragma unroll
    for (int v = 0; v < 32; v++) {
        float2 cs = __ldg(ct + v * 16 + lp);
        ull c2 = pk(cs.x, cs.x);
        ull s2 = pk(cs.y, cs.y) ^ smask;
#pragma unroll
        for (int h = 0; h < 2; h++) {
            ull x = val[v * 2 + h];
            ull xp = __shfl_xor_sync(0xffffffffu, x, LM);
            val[v * 2 + h] = f2fma(c2, x, f2mul(s2, xp));
        }
        if ((v & 3) == 3) cfence();
    }
}

__device__ __forceinline__ void quintic(ull (&val)[64], int lane, int act) {
    const float4* __restrict__ qa = g_qa + act * 1024;
    const float2* __restrict__ qs = g_qs + act * 1024;
    const ull C1875 = 0x3FF000003FF00000ULL;  // (1.875, 1.875)
    const ull CM125 = 0xBFA00000BFA00000ULL;  // (-1.25, -1.25)
    const ull C0375 = 0x3EC000003EC00000ULL;  // (0.375, 0.375)
#pragma unroll
    for (int v = 0; v < 32; v++) {
        float4 aq = __ldg(qa + v * 32 + lane);
        float2 sq = __ldg(qs + v * 32 + lane);
        ull m2 = pk(aq.x, aq.y);
        ull nb2 = pk(aq.z, aq.w);
        ull sc2 = pk(sq.x, sq.y);
#pragma unroll
        for (int h = 0; h < 2; h++) {
            ull u = f2fma(val[v * 2 + h], m2, nb2);
            float lo, hi;
            unpk(u, lo, hi);
            lo = fminf(fmaxf(lo, -1.0f), 1.0f);
            hi = fminf(fmaxf(hi, -1.0f), 1.0f);
            u = pk(lo, hi);
            ull u2 = f2mul(u, u);
            ull p = f2fma(u2, C0375, CM125);
            p = f2fma(u2, p, C1875);
            ull r = f2mul(u, p);
            val[v * 2 + h] = f2mul(r, sc2);
        }
        if ((v & 7) == 7) cfence();
    }
}

__global__ void __launch_bounds__(128, 1)
net_kernel(const float* __restrict__ X, float* __restrict__ Y) {
    const int lane = threadIdx.x & 31;
    const int w = blockIdx.x * 4 + (threadIdx.x >> 5);
    const long long row0 = (long long)w * 4;
    const float* __restrict__ xr0 = X + row0 * WIDTH;
    const float* __restrict__ xr1 = xr0 + WIDTH;
    const float* __restrict__ xr2 = xr1 + WIDTH;
    const float* __restrict__ xr3 = xr2 + WIDTH;

    ull val[64];

    // load: 4 rows, packed (row0,row1) -> h=0, (row2,row3) -> h=1
#pragma unroll
    for (int vhi = 0; vhi < 8; vhi++) {
        int off = vhi * 128 + lane * 4;
        int s = vhi * 4;
        {
            float4 a = *(const float4*)(xr0 + off);
            float4 b = *(const float4*)(xr1 + off);
            val[(s + 0) * 2 + 0] = pk(a.x, b.x);
            val[(s + 1) * 2 + 0] = pk(a.y, b.y);
            val[(s + 2) * 2 + 0] = pk(a.z, b.z);
            val[(s + 3) * 2 + 0] = pk(a.w, b.w);
        }
        cfence();
        {
            float4 c = *(const float4*)(xr2 + off);
            float4 d = *(const float4*)(xr3 + off);
            val[(s + 0) * 2 + 1] = pk(c.x, d.x);
            val[(s + 1) * 2 + 1] = pk(c.y, d.y);
            val[(s + 2) * 2 + 1] = pk(c.z, d.z);
            val[(s + 3) * 2 + 1] = pk(c.w, d.w);
        }
        cfence();
    }

#pragma unroll 1
    for (int layer = 0; layer < DEPTH; layer++) {
        const float2* __restrict__ ct = g_ctab + layer * (BDEPTH * 512);
        reg_step<16>(val, lane, ct + 0 * 512);   // t=0: bit 9
        reg_step<8>(val, lane, ct + 1 * 512);    // t=1: bit 8
        reg_step<4>(val, lane, ct + 2 * 512);    // t=2: bit 7
        lane_step<16>(val, lane, ct + 3 * 512);  // t=3: bit 6
        lane_step<8>(val, lane, ct + 4 * 512);   // t=4: bit 5
        lane_step<4>(val, lane, ct + 5 * 512);   // t=5: bit 4
        lane_step<2>(val, lane, ct + 6 * 512);   // t=6: bit 3
        lane_step<1>(val, lane, ct + 7 * 512);   // t=7: bit 2
        reg_step<2>(val, lane, ct + 8 * 512);    // t=8: bit 1
        reg_step<1>(val, lane, ct + 9 * 512);    // t=9: bit 0
        if (layer < DEPTH - 1) quintic(val, lane, layer);
    }

    // store (final permutation is identity: 80 steps = 8 full index rotations)
    float* __restrict__ yr0 = Y + row0 * WIDTH;
    float* __restrict__ yr1 = yr0 + WIDTH;
    float* __restrict__ yr2 = yr1 + WIDTH;
    float* __restrict__ yr3 = yr2 + WIDTH;
#pragma unroll
    for (int vhi = 0; vhi < 8; vhi++) {
        int off = vhi * 128 + lane * 4;
        int s = vhi * 4;
        {
            float4 a, b;
            unpk(val[(s + 0) * 2 + 0], a.x, b.x);
            unpk(val[(s + 1) * 2 + 0], a.y, b.y);
            unpk(val[(s + 2) * 2 + 0], a.z, b.z);
            unpk(val[(s + 3) * 2 + 0], a.w, b.w);
            *(float4*)(yr0 + off) = a;
            *(float4*)(yr1 + off) = b;
        }
        cfence();
        {
            float4 c, d;
            unpk(val[(s + 0) * 2 + 1], c.x, d.x);
            unpk(val[(s + 1) * 2 + 1], c.y, d.y);
            unpk(val[(s + 2) * 2 + 1], c.z, d.z);
            unpk(val[(s + 3) * 2 + 1], c.w, d.w);
            *(float4*)(yr2 + off) = c;
            *(float4*)(yr3 + off) = d;
        }
        cfence();
    }
}

extern "C" void kernel_launch(void* const* d_in, const int* in_sizes, int n_in,
                              void* d_out, int out_size) {
    const float* X     = (const float*)d_in[0];
    const float* bp    = (const float*)d_in[1];
    const float* bias  = (const float*)d_in[2];
    const float* slope = (const float*)d_in[3];
    const float* scale = (const float*)d_in[4];
    float* Y = (float*)d_out;

    // ONE prep launch (2 launches total, so ncu -s 5 -c 1 profiles net_kernel)
    prep_all<<<(CT_ELEMS + Q_ELEMS + 255) / 256, 256>>>(bp, bias, slope, scale);
    // 4 rows per warp, 4 warps per CTA -> 16 rows per CTA
    net_kernel<<<BATCH / 16, 128>>>(X, Y);
}

// round 5
// speedup vs baseline: 1.0750x; 1.0750x over previous
#include <cuda_runtime.h>
#include <cstdint>

#define WIDTH  1024
#define HALF   512
#define DEPTH  8
#define BDEPTH 10
#define BATCH  65536

typedef unsigned long long ull;

// Layout: lane = (rl<<3)|lp  (rl: row selector 0..3, lp: 3 position bits)
//         position p = (v<<4) | (lp<<1) | a   (v: 64 regs, a: f32x2 half)
// Each thread owns ONE row (128 floats = 64 f32x2).
// Steps per layer: t=0..5 reg (v bit 5-t), t=6..8 lane (lp bit 8-t), t=9 intra (a).
//
// Butterfly tables: 256 float4 per step.
//   reg step  (t<=5): e = pi*8 + lp,  float4 = (c_a0, c_a1, s_a0, s_a1)
//   lane step (6<=t<=8): e = v*4 + lpp, float4 = (c_a0, c_a1, s_a0, s_a1)
//   intra     (t==9): float2 view, idx = v*8 + lp -> (c, s)
__device__ float4 g_ctab[DEPTH * BDEPTH * 256];
// quintic: e = v*8+lp : (m0, m1, nb0, nb1) and (sc0, sc1) for the two f32x2 halves
__device__ float4 g_qa[(DEPTH - 1) * 512];
__device__ float2 g_qs[(DEPTH - 1) * 512];

// ---------- f32x2 helpers ----------
__device__ __forceinline__ ull pk(float lo, float hi) {
    ull r;
    asm("mov.b64 %0, {%1, %2};" : "=l"(r) : "r"(__float_as_uint(lo)), "r"(__float_as_uint(hi)));
    return r;
}
__device__ __forceinline__ void unpk(ull v, float& lo, float& hi) {
    unsigned a, b;
    asm("mov.b64 {%0, %1}, %2;" : "=r"(a), "=r"(b) : "l"(v));
    lo = __uint_as_float(a);
    hi = __uint_as_float(b);
}
__device__ __forceinline__ ull f2mul(ull a, ull b) {
    ull r;
    asm("mul.rn.f32x2 %0, %1, %2;" : "=l"(r) : "l"(a), "l"(b));
    return r;
}
__device__ __forceinline__ ull f2fma(ull a, ull b, ull c) {
    ull r;
    asm("fma.rn.f32x2 %0, %1, %2, %3;" : "=l"(r) : "l"(a), "l"(b), "l"(c));
    return r;
}
__device__ __forceinline__ void cfence() { asm volatile("" ::: "memory"); }

// ---------- prep ----------
#define BT_ELEMS (DEPTH * BDEPTH * 256)
#define QT_ELEMS ((DEPTH - 1) * 512)

__device__ __forceinline__ float theta_of(const float* bp, int layer, int t, int p0) {
    int j = 0;
#pragma unroll
    for (int k = 0; k < 9; k++) {
        int src = ((k - t) % 10 + 10) % 10;
        j |= ((p0 >> src) & 1) << k;
    }
    return bp[layer * (HALF * BDEPTH) + j * BDEPTH + t];
}

__global__ void prep_all(const float* __restrict__ bp,
                         const float* __restrict__ bias,
                         const float* __restrict__ slope,
                         const float* __restrict__ scale) {
    int e0 = blockIdx.x * blockDim.x + threadIdx.x;
    if (e0 < BT_ELEMS) {
        int T = e0 >> 8;          // global step
        int e = e0 & 255;
        int layer = T / BDEPTH;
        int t = T % BDEPTH;

        if (t <= 5) {
            // reg step: pairs v-bit (5 - t)
            int M = 1 << (5 - t);
            int pi = e >> 3;
            int lp = e & 7;
            int v0 = (pi & (M - 1)) | ((pi & ~(M - 1)) << 1);
            float c0, s0, c1, s1;
            {
                int p0 = (v0 << 4) | (lp << 1) | 0;
                float th = theta_of(bp, layer, t, p0);
                sincosf(th, &s0, &c0);
            }
            {
                int p0 = (v0 << 4) | (lp << 1) | 1;
                float th = theta_of(bp, layer, t, p0);
                sincosf(th, &s1, &c1);
            }
            g_ctab[e0] = make_float4(c0, c1, s0, s1);
        } else if (t <= 8) {
            // lane step: pairs lp-bit (8 - t)
            int LM = 1 << (8 - t);
            int v = e >> 2;
            int lpp = e & 3;
            int l0 = (lpp & (LM - 1)) | ((lpp & ~(LM - 1)) << 1);
            float c0, s0, c1, s1;
            {
                int p0 = (v << 4) | (l0 << 1) | 0;
                float th = theta_of(bp, layer, t, p0);
                sincosf(th, &s0, &c0);
            }
            {
                int p0 = (v << 4) | (l0 << 1) | 1;
                float th = theta_of(bp, layer, t, p0);
                sincosf(th, &s1, &c1);
            }
            g_ctab[e0] = make_float4(c0, c1, s0, s1);
        } else {
            // intra step: float4 slot e holds float2 entries 2e, 2e+1 of idx = v*8+lp
            float comp[4];
#pragma unroll
            for (int k = 0; k < 2; k++) {
                int idx = 2 * e + k;
                int v = idx >> 3;
                int lp = idx & 7;
                int p0 = (v << 4) | (lp << 1);  // a = 0 member
                float th = theta_of(bp, layer, t, p0);
                float s, c;
                sincosf(th, &s, &c);
                comp[k * 2] = c;
                comp[k * 2 + 1] = s;
            }
            g_ctab[e0] = make_float4(comp[0], comp[1], comp[2], comp[3]);
        }
    } else if (e0 < BT_ELEMS + QT_ELEMS) {
        int q = e0 - BT_ELEMS;
        int act = q >> 9;
        int idx = q & 511;
        int v = idx >> 3;
        int lp = idx & 7;
        int p0 = (v << 4) | (lp << 1);
        int p1 = p0 | 1;
        float bi0 = bias[act * WIDTH + p0], bi1 = bias[act * WIDTH + p1];
        float sl0 = slope[act * WIDTH + p0], sl1 = slope[act * WIDTH + p1];
        float sc0 = scale[act * WIDTH + p0], sc1 = scale[act * WIDTH + p1];
        g_qa[q] = make_float4(sl0 / sc0, sl1 / sc1, -bi0 / sc0, -bi1 / sc1);
        g_qs[q] = make_float2(sc0, sc1);
    }
}

// ---------- main kernel ----------

template <int M>
__device__ __forceinline__ void reg_step(ull (&val)[64], int lp, const float4* __restrict__ ct) {
#pragma unroll
    for (int pi = 0; pi < 32; pi++) {
        const int v0 = (pi & (M - 1)) | ((pi & ~(M - 1)) << 1);
        const int v1 = v0 | M;
        float4 cs = __ldg(ct + pi * 8 + lp);
        ull c2 = pk(cs.x, cs.y);
        ull s2 = pk(cs.z, cs.w);
        ull ns2 = s2 ^ 0x8000000080000000ULL;
        ull x0 = val[v0];
        ull x1 = val[v1];
        val[v0] = f2fma(c2, x0, f2mul(s2, x1));   // n0 =  c*x0 + s*x1
        val[v1] = f2fma(c2, x1, f2mul(ns2, x0));  // n1 =  c*x1 - s*x0
        if ((pi & 3) == 3) cfence();
    }
}

template <int LM>
__device__ __forceinline__ void lane_step(ull (&val)[64], int lane, int lp,
                                          const float4* __restrict__ ct) {
    const ull smask = (lp & LM) ? 0x8000000080000000ULL : 0ULL;
    const int lpp = (lp & (LM - 1)) | ((lp >> 1) & ~(LM - 1));
#pragma unroll
    for (int v = 0; v < 64; v++) {
        float4 cs = __ldg(ct + v * 4 + lpp);
        ull c2 = pk(cs.x, cs.y);
        ull s2 = pk(cs.z, cs.w) ^ smask;
        ull x = val[v];
        ull xp = __shfl_xor_sync(0xffffffffu, x, LM);
        val[v] = f2fma(c2, x, f2mul(s2, xp));
        if ((v & 7) == 7) cfence();
    }
}

__device__ __forceinline__ void intra_step(ull (&val)[64], int lp, const float4* __restrict__ ct) {
    const float2* __restrict__ ci = (const float2*)ct;
#pragma unroll
    for (int v = 0; v < 64; v++) {
        float2 cs = __ldg(ci + v * 8 + lp);
        ull c2 = pk(cs.x, cs.x);
        ull spm = pk(cs.y, -cs.y);  // (s, -s)
        ull x = val[v];
        float lo, hi;
        unpk(x, lo, hi);
        ull xsw = pk(hi, lo);
        // lo: c*x0 + s*x1 ; hi: c*x1 - s*x0
        val[v] = f2fma(c2, x, f2mul(spm, xsw));
        if ((v & 7) == 7) cfence();
    }
}

__device__ __forceinline__ void quintic(ull (&val)[64], int lp, int act) {
    const float4* __restrict__ qa = g_qa + act * 512;
    const float2* __restrict__ qs = g_qs + act * 512;
    const ull C1875 = 0x3FF000003FF00000ULL;  // (1.875, 1.875)
    const ull CM125 = 0xBFA00000BFA00000ULL;  // (-1.25, -1.25)
    const ull C0375 = 0x3EC000003EC00000ULL;  // (0.375, 0.375)
#pragma unroll
    for (int v = 0; v < 64; v++) {
        float4 aq = __ldg(qa + v * 8 + lp);
        float2 sq = __ldg(qs + v * 8 + lp);
        ull m2 = pk(aq.x, aq.y);
        ull nb2 = pk(aq.z, aq.w);
        ull sc2 = pk(sq.x, sq.y);
        ull u = f2fma(val[v], m2, nb2);
        float lo, hi;
        unpk(u, lo, hi);
        lo = fminf(fmaxf(lo, -1.0f), 1.0f);
        hi = fminf(fmaxf(hi, -1.0f), 1.0f);
        u = pk(lo, hi);
        ull u2 = f2mul(u, u);
        ull p = f2fma(u2, C0375, CM125);
        p = f2fma(u2, p, C1875);
        val[v] = f2mul(f2mul(u, p), sc2);
        if ((v & 7) == 7) cfence();
    }
}

__global__ void __launch_bounds__(128, 1)
net_kernel(const float* __restrict__ X, float* __restrict__ Y) {
    const int lane = threadIdx.x & 31;
    const int lp = lane & 7;        // 3 position bits
    const int rl = lane >> 3;       // row selector 0..3
    const int w = blockIdx.x * 4 + (threadIdx.x >> 5);
    const long long row = (long long)w * 4 + rl;

    // load: thread owns one full row; val[v] = (p = v*16+lp*2, p+1)
    const ull* __restrict__ xr = (const ull*)(X + row * WIDTH);
    ull val[64];
#pragma unroll
    for (int v = 0; v < 64; v++) {
        val[v] = __ldg(xr + v * 8 + lp);
        if ((v & 7) == 7) cfence();
    }

#pragma unroll 1
    for (int layer = 0; layer < DEPTH; layer++) {
        const float4* __restrict__ ct = g_ctab + layer * (BDEPTH * 256);
        reg_step<32>(val, lp, ct + 0 * 256);       // t=0: p bit 9 (v bit 5)
        reg_step<16>(val, lp, ct + 1 * 256);       // t=1: p bit 8
        reg_step<8>(val, lp, ct + 2 * 256);        // t=2: p bit 7
        reg_step<4>(val, lp, ct + 3 * 256);        // t=3: p bit 6
        reg_step<2>(val, lp, ct + 4 * 256);        // t=4: p bit 5
        reg_step<1>(val, lp, ct + 5 * 256);        // t=5: p bit 4
        lane_step<4>(val, lane, lp, ct + 6 * 256); // t=6: p bit 3 (lp bit 2)
        lane_step<2>(val, lane, lp, ct + 7 * 256); // t=7: p bit 2
        lane_step<1>(val, lane, lp, ct + 8 * 256); // t=8: p bit 1
        intra_step(val, lp, ct + 9 * 256);         // t=9: p bit 0 (f32x2 half)
        if (layer < DEPTH - 1) quintic(val, lp, layer);
    }

    // store (net permutation across each layer is identity)
    ull* __restrict__ yr = (ull*)(Y + row * WIDTH);
#pragma unroll
    for (int v = 0; v < 64; v++) {
        yr[v * 8 + lp] = val[v];
        if ((v & 7) == 7) cfence();
    }
}

extern "C" void kernel_launch(void* const* d_in, const int* in_sizes, int n_in,
                              void* d_out, int out_size) {
    const float* X     = (const float*)d_in[0];
    const float* bp    = (const float*)d_in[1];
    const float* bias  = (const float*)d_in[2];
    const float* slope = (const float*)d_in[3];
    const float* scale = (const float*)d_in[4];
    float* Y = (float*)d_out;

    prep_all<<<(BT_ELEMS + QT_ELEMS + 255) / 256, 256>>>(bp, bias, slope, scale);
    // one row per thread, 4 rows per warp, 16 rows per CTA
    net_kernel<<<BATCH / 16, 128>>>(X, Y);
}

// round 6
// speedup vs baseline: 1.2543x; 1.1668x over previous
#include <cuda_runtime.h>
#include <cstdint>

#define WIDTH  1024
#define HALF   512
#define DEPTH  8
#define BDEPTH 10
#define BATCH  65536

typedef unsigned long long ull;

// Geometry (same as the 760us kernel):
//   lane = p bits [6:2]  (32 lanes)
//   slot v (0..31): p = ((v>>2)<<7) | (lane<<2) | (v&3)   -> v bits = p bits {1,0,9,8,7}
//   thread holds val[v*2+h]: h=0 rows(0,1), h=1 rows(2,3) packed in f32x2.
// Steps t (bit b = 9-t): t=0,1,2 reg (v bits 4,3,2); t=3..7 lane (lane bits 4..0);
//                        t=8,9 reg (v bits 1,0).
//
// Butterfly table: 256 float4 per step (4KB), ALL fetched via LDG.128:
//   reg step:  entry[e*32 + lane], e=0..7:  (c[pi=2e], s[2e], c[2e+1], s[2e+1])
//   lane step: entry[e*16 + lp],  e=0..15: (c[v=2e],  s[2e], c[2e+1], s[2e+1])
__device__ float4 g_bt[DEPTH * BDEPTH * 256];
// quintic: entry[act*1024 + v*32 + lane] = (m, nb, sc, 0), m=slope/scale, nb=-bias/scale
__device__ float4 g_qt[(DEPTH - 1) * 1024];

// ---------- f32x2 helpers ----------
__device__ __forceinline__ ull pk(float lo, float hi) {
    ull r;
    asm("mov.b64 %0, {%1, %2};" : "=l"(r) : "r"(__float_as_uint(lo)), "r"(__float_as_uint(hi)));
    return r;
}
__device__ __forceinline__ void unpk(ull v, float& lo, float& hi) {
    unsigned a, b;
    asm("mov.b64 {%0, %1}, %2;" : "=r"(a), "=r"(b) : "l"(v));
    lo = __uint_as_float(a);
    hi = __uint_as_float(b);
}
__device__ __forceinline__ ull f2mul(ull a, ull b) {
    ull r;
    asm("mul.rn.f32x2 %0, %1, %2;" : "=l"(r) : "l"(a), "l"(b));
    return r;
}
__device__ __forceinline__ ull f2fma(ull a, ull b, ull c) {
    ull r;
    asm("fma.rn.f32x2 %0, %1, %2, %3;" : "=l"(r) : "l"(a), "l"(b), "l"(c));
    return r;
}
__device__ __forceinline__ void cfence() { asm volatile("" ::: "memory"); }

// ---------- prep ----------
#define BT_ELEMS (DEPTH * BDEPTH * 256)
#define QT_ELEMS ((DEPTH - 1) * 1024)

__device__ __forceinline__ float theta_of(const float* bp, int layer, int t, int p0) {
    int j = 0;
#pragma unroll
    for (int k = 0; k < 9; k++) {
        int src = ((k - t) % 10 + 10) % 10;
        j |= ((p0 >> src) & 1) << k;
    }
    return bp[layer * (HALF * BDEPTH) + j * BDEPTH + t];
}

__global__ void prep_all(const float* __restrict__ bp,
                         const float* __restrict__ bias,
                         const float* __restrict__ slope,
                         const float* __restrict__ scale) {
    int e0 = blockIdx.x * blockDim.x + threadIdx.x;
    if (e0 < BT_ELEMS) {
        int T = e0 >> 8;
        int idx = e0 & 255;
        int layer = T / BDEPTH;
        int t = T % BDEPTH;
        int b = 9 - t;

        float4 out;
        if (b >= 7 || b <= 1) {
            // reg step: entry[e*32 + lane], pairs pi = 2e, 2e+1
            int sbit = (b >= 7) ? (b - 5) : b;
            int m = 1 << sbit;
            int e = idx >> 5;
            int lane = idx & 31;
            float cs[4];
#pragma unroll
            for (int k = 0; k < 2; k++) {
                int pi = 2 * e + k;
                int v0 = (pi & (m - 1)) | ((pi & ~(m - 1)) << 1);
                int p0 = ((v0 >> 2) << 7) | (lane << 2) | (v0 & 3);
                float th = theta_of(bp, layer, t, p0);
                float s, c;
                sincosf(th, &s, &c);
                cs[2 * k] = c;
                cs[2 * k + 1] = s;
            }
            out = make_float4(cs[0], cs[1], cs[2], cs[3]);
        } else {
            // lane step: entry[e*16 + lp], slots v = 2e, 2e+1
            int lm = 1 << (b - 2);
            int e = idx >> 4;
            int lp = idx & 15;
            int l0 = (lp & (lm - 1)) | ((lp & ~(lm - 1)) << 1);
            float cs[4];
#pragma unroll
            for (int k = 0; k < 2; k++) {
                int v = 2 * e + k;
                int p0 = ((v >> 2) << 7) | (l0 << 2) | (v & 3);
                float th = theta_of(bp, layer, t, p0);
                float s, c;
                sincosf(th, &s, &c);
                cs[2 * k] = c;
                cs[2 * k + 1] = s;
            }
            out = make_float4(cs[0], cs[1], cs[2], cs[3]);
        }
        g_bt[e0] = out;
    } else if (e0 < BT_ELEMS + QT_ELEMS) {
        int q = e0 - BT_ELEMS;
        int act = q >> 10;
        int idx = q & 1023;
        int v = idx >> 5;
        int l = idx & 31;
        int p0 = ((v >> 2) << 7) | (l << 2) | (v & 3);
        float bi = bias[act * WIDTH + p0];
        float sl = slope[act * WIDTH + p0];
        float sc = scale[act * WIDTH + p0];
        g_qt[q] = make_float4(sl / sc, -bi / sc, sc, 0.0f);
    }
}

// ---------- main kernel ----------

__device__ __forceinline__ void bfly_pair(ull (&val)[64], int v0, int v1, float c, float s) {
    ull c2 = pk(c, c);
    ull s2 = pk(s, s);
    ull ns2 = s2 ^ 0x8000000080000000ULL;
#pragma unroll
    for (int h = 0; h < 2; h++) {
        ull x0 = val[v0 * 2 + h];
        ull x1 = val[v1 * 2 + h];
        val[v0 * 2 + h] = f2fma(c2, x0, f2mul(s2, x1));   // n0 =  c*x0 + s*x1
        val[v1 * 2 + h] = f2fma(c2, x1, f2mul(ns2, x0));  // n1 =  c*x1 - s*x0
    }
}

template <int M>
__device__ __forceinline__ void reg_step(ull (&val)[64], int lane, const float4* __restrict__ bt) {
#pragma unroll
    for (int e = 0; e < 8; e++) {
        float4 q = __ldg(bt + e * 32 + lane);
        {
            const int pi = 2 * e;
            const int v0 = (pi & (M - 1)) | ((pi & ~(M - 1)) << 1);
            bfly_pair(val, v0, v0 | M, q.x, q.y);
        }
        {
            const int pi = 2 * e + 1;
            const int v0 = (pi & (M - 1)) | ((pi & ~(M - 1)) << 1);
            bfly_pair(val, v0, v0 | M, q.z, q.w);
        }
        if (e & 1) cfence();
    }
}

template <int LM>
__device__ __forceinline__ void lane_step(ull (&val)[64], int lane, const float4* __restrict__ bt) {
    const ull smask = (lane & LM) ? 0x8000000080000000ULL : 0ULL;
    const int lp = (lane & (LM - 1)) | ((lane >> 1) & ~(LM - 1));
#pragma unroll
    for (int e = 0; e < 16; e++) {
        float4 q = __ldg(bt + e * 16 + lp);
#pragma unroll
        for (int k = 0; k < 2; k++) {
            const int v = 2 * e + k;
            float c = k ? q.z : q.x;
            float s = k ? q.w : q.y;
            ull c2 = pk(c, c);
            ull s2 = pk(s, s) ^ smask;
#pragma unroll
            for (int h = 0; h < 2; h++) {
                ull x = val[v * 2 + h];
                ull xp = __shfl_xor_sync(0xffffffffu, x, LM);
                val[v * 2 + h] = f2fma(c2, x, f2mul(s2, xp));
            }
        }
        if (e & 1) cfence();
    }
}

__device__ __forceinline__ void quintic(ull (&val)[64], int lane, int act) {
    const float4* __restrict__ qt = g_qt + act * 1024;
    const ull C1875 = 0x3FF000003FF00000ULL;  // (1.875, 1.875)
    const ull CM125 = 0xBFA00000BFA00000ULL;  // (-1.25, -1.25)
    const ull C0375 = 0x3EC000003EC00000ULL;  // (0.375, 0.375)
#pragma unroll
    for (int v = 0; v < 32; v++) {
        float4 q = __ldg(qt + v * 32 + lane);
        ull m2 = pk(q.x, q.x);
        ull nb2 = pk(q.y, q.y);
        ull sc2 = pk(q.z, q.z);
#pragma unroll
        for (int h = 0; h < 2; h++) {
            ull u = f2fma(val[v * 2 + h], m2, nb2);
            float lo, hi;
            unpk(u, lo, hi);
            lo = fminf(fmaxf(lo, -1.0f), 1.0f);
            hi = fminf(fmaxf(hi, -1.0f), 1.0f);
            u = pk(lo, hi);
            ull u2 = f2mul(u, u);
            ull p = f2fma(u2, C0375, CM125);
            p = f2fma(u2, p, C1875);
            val[v * 2 + h] = f2mul(f2mul(u, p), sc2);
        }
        if ((v & 7) == 7) cfence();
    }
}

__global__ void __launch_bounds__(128, 1)
net_kernel(const float* __restrict__ X, float* __restrict__ Y) {
    const int lane = threadIdx.x & 31;
    const int w = blockIdx.x * 4 + (threadIdx.x >> 5);
    const long long row0 = (long long)w * 4;
    const float* __restrict__ xr0 = X + row0 * WIDTH;
    const float* __restrict__ xr1 = xr0 + WIDTH;
    const float* __restrict__ xr2 = xr1 + WIDTH;
    const float* __restrict__ xr3 = xr2 + WIDTH;

    ull val[64];

    // load: 4 rows; val[v*2+h]: h=0 -> (row0,row1), h=1 -> (row2,row3)
#pragma unroll
    for (int vhi = 0; vhi < 8; vhi++) {
        int off = vhi * 128 + lane * 4;
        int s = vhi * 4;
        {
            float4 a = *(const float4*)(xr0 + off);
            float4 b = *(const float4*)(xr1 + off);
            val[(s + 0) * 2 + 0] = pk(a.x, b.x);
            val[(s + 1) * 2 + 0] = pk(a.y, b.y);
            val[(s + 2) * 2 + 0] = pk(a.z, b.z);
            val[(s + 3) * 2 + 0] = pk(a.w, b.w);
        }
        cfence();
        {
            float4 c = *(const float4*)(xr2 + off);
            float4 d = *(const float4*)(xr3 + off);
            val[(s + 0) * 2 + 1] = pk(c.x, d.x);
            val[(s + 1) * 2 + 1] = pk(c.y, d.y);
            val[(s + 2) * 2 + 1] = pk(c.z, d.z);
            val[(s + 3) * 2 + 1] = pk(c.w, d.w);
        }
        cfence();
    }

#pragma unroll 1
    for (int layer = 0; layer < DEPTH; layer++) {
        const float4* __restrict__ bt = g_bt + layer * (BDEPTH * 256);
        reg_step<16>(val, lane, bt + 0 * 256);   // t=0: p bit 9 (v bit 4)
        reg_step<8>(val, lane, bt + 1 * 256);    // t=1: p bit 8 (v bit 3)
        reg_step<4>(val, lane, bt + 2 * 256);    // t=2: p bit 7 (v bit 2)
        lane_step<16>(val, lane, bt + 3 * 256);  // t=3: p bit 6 (lane bit 4)
        lane_step<8>(val, lane, bt + 4 * 256);   // t=4: p bit 5
        lane_step<4>(val, lane, bt + 5 * 256);   // t=5: p bit 4
        lane_step<2>(val, lane, bt + 6 * 256);   // t=6: p bit 3
        lane_step<1>(val, lane, bt + 7 * 256);   // t=7: p bit 2 (lane bit 0)
        reg_step<2>(val, lane, bt + 8 * 256);    // t=8: p bit 1 (v bit 1)
        reg_step<1>(val, lane, bt + 9 * 256);    // t=9: p bit 0 (v bit 0)
        if (layer < DEPTH - 1) quintic(val, lane, layer);
    }

    // store (net permutation over 10 steps per layer is identity)
    float* __restrict__ yr0 = Y + row0 * WIDTH;
    float* __restrict__ yr1 = yr0 + WIDTH;
    float* __restrict__ yr2 = yr1 + WIDTH;
    float* __restrict__ yr3 = yr2 + WIDTH;
#pragma unroll
    for (int vhi = 0; vhi < 8; vhi++) {
        int off = vhi * 128 + lane * 4;
        int s = vhi * 4;
        {
            float4 a, b;
            unpk(val[(s + 0) * 2 + 0], a.x, b.x);
            unpk(val[(s + 1) * 2 + 0], a.y, b.y);
            unpk(val[(s + 2) * 2 + 0], a.z, b.z);
            unpk(val[(s + 3) * 2 + 0], a.w, b.w);
            *(float4*)(yr0 + off) = a;
            *(float4*)(yr1 + off) = b;
        }
        cfence();
        {
            float4 c, d;
            unpk(val[(s + 0) * 2 + 1], c.x, d.x);
            unpk(val[(s + 1) * 2 + 1], c.y, d.y);
            unpk(val[(s + 2) * 2 + 1], c.z, d.z);
            unpk(val[(s + 3) * 2 + 1], c.w, d.w);
            *(float4*)(yr2 + off) = c;
            *(float4*)(yr3 + off) = d;
        }
        cfence();
    }
}

extern "C" void kernel_launch(void* const* d_in, const int* in_sizes, int n_in,
                              void* d_out, int out_size) {
    const float* X     = (const float*)d_in[0];
    const float* bp    = (const float*)d_in[1];
    const float* bias  = (const float*)d_in[2];
    const float* slope = (const float*)d_in[3];
    const float* scale = (const float*)d_in[4];
    float* Y = (float*)d_out;

    prep_all<<<(BT_ELEMS + QT_ELEMS + 255) / 256, 256>>>(bp, bias, slope, scale);
    // 4 rows per warp, 4 warps per CTA -> 16 rows per CTA
    net_kernel<<<BATCH / 16, 128>>>(X, Y);
}